// round 8
// baseline (speedup 1.0000x reference)
#include <cuda_runtime.h>
#include <cuda_bf16.h>

// GlobalAttentionLayer, single fused pass, SINGLE LAUNCH (R8).
// pooled[b] = sum_n e^{g_n} * (states_n @ Wo + bo) / (sum_n e^{g_n} + eps)
//
// R8 vs R7: global work-stealing tile queue (8-node tiles, atomicAdd fetch
// with next-tile prefetch) instead of one static contiguous chunk per warp.
// Targets the ~18% DRAM-idle tail caused by per-SM finishing-time spread.
// Accumulators carry across a warp's (monotonically increasing) tiles;
// sorted ids => seg[tileEnd-1]==cur means the whole tile is in segment cur
// (branch-free fast path, same x2 body as R7).
//
// Inputs (metadata order):
//   d_in[0] states  float32 [N, 256]
//   d_in[1] seg_ids int32   [N]   (sorted)
//   d_in[2] Wg float32 [256,1]   d_in[3] bg float32 [1]
//   d_in[4] Wo float32 [256,2]   d_in[5] bo float32 [2]
// Output: float32 [B, 2], B = out_size/2

#define NBLOCKS  592
#define NTHREADS 256
#define MAXB     1024
#define TILE     8

__device__ float        g_accS [MAXB];   // zero at module load; epilogue re-zeros
__device__ float        g_accV0[MAXB];
__device__ float        g_accV1[MAXB];
__device__ unsigned int g_work;          // work-queue head; epilogue re-zeros
__device__ unsigned int g_done;          // CTA-done counter; epilogue re-zeros

__global__ __launch_bounds__(NTHREADS) void ga_main(
    const float* __restrict__ states,
    const int*   __restrict__ seg,
    const float* __restrict__ Wg,
    const float* __restrict__ bg,
    const float* __restrict__ Wo,
    const float* __restrict__ bo,
    float* __restrict__ out,
    int N, int B)
{
    const int lane = threadIdx.x & 31;

    const float bgv = bg[0];
    const float bo0 = bo[0];
    const float bo1 = bo[1];

    // Per-lane slice of the weight vectors: columns [lane*8, lane*8+8)
    const int c0 = lane * 8;
    float wg[8], wo0[8], wo1[8];
#pragma unroll
    for (int j = 0; j < 8; j++) {
        wg [j] = Wg[c0 + j];
        wo0[j] = Wo[(c0 + j) * 2 + 0];
        wo1[j] = Wo[(c0 + j) * 2 + 1];
    }

    const float4* base = reinterpret_cast<const float4*>(states);
    const int numTiles = (N + TILE - 1) / TILE;

    int   cur = -1;                  // current segment (-1 = none yet)
    float aS  = 0.0f;                // sum of e (lane-uniform)
    float aV0 = 0.0f, aV1 = 0.0f;    // per-lane partials of e * p_lane

#define FLUSH(SEGID)                                                        \
    do {                                                                    \
        float _v0 = aV0, _v1 = aV1;                                         \
        _Pragma("unroll")                                                   \
        for (int _o = 16; _o; _o >>= 1) {                                   \
            _v0 += __shfl_xor_sync(0xFFFFFFFFu, _v0, _o);                   \
            _v1 += __shfl_xor_sync(0xFFFFFFFFu, _v1, _o);                   \
        }                                                                   \
        if (lane == 0) {                                                    \
            atomicAdd(&g_accS [SEGID], aS);                                 \
            atomicAdd(&g_accV0[SEGID], fmaf(bo0, aS, _v0));                 \
            atomicAdd(&g_accV1[SEGID], fmaf(bo1, aS, _v1));                 \
        }                                                                   \
        aS = 0.0f; aV0 = 0.0f; aV1 = 0.0f;                                  \
    } while (0)

    // per-node accumulate (no boundary logic)
#define NODE2(M)                                                            \
    do {                                                                    \
        const float4* r0 = base + (size_t)((M) + 0) * 64 + lane * 2;        \
        const float4* r1 = base + (size_t)((M) + 1) * 64 + lane * 2;        \
        float4 xa0 = r0[0];                                                 \
        float4 xb0 = r0[1];                                                 \
        float4 xa1 = r1[0];                                                 \
        float4 xb1 = r1[1];                                                 \
        float x0[8] = {xa0.x, xa0.y, xa0.z, xa0.w,                          \
                       xb0.x, xb0.y, xb0.z, xb0.w};                         \
        float x1[8] = {xa1.x, xa1.y, xa1.z, xa1.w,                          \
                       xb1.x, xb1.y, xb1.z, xb1.w};                         \
        float g0 = 0.f, p00 = 0.f, p10 = 0.f;                               \
        float g1 = 0.f, p01 = 0.f, p11 = 0.f;                               \
        _Pragma("unroll")                                                   \
        for (int j = 0; j < 8; j++) {                                       \
            g0  = fmaf(x0[j], wg [j], g0);                                  \
            g1  = fmaf(x1[j], wg [j], g1);                                  \
            p00 = fmaf(x0[j], wo0[j], p00);                                 \
            p01 = fmaf(x1[j], wo0[j], p01);                                 \
            p10 = fmaf(x0[j], wo1[j], p10);                                 \
            p11 = fmaf(x1[j], wo1[j], p11);                                 \
        }                                                                   \
        _Pragma("unroll")                                                   \
        for (int off = 16; off; off >>= 1) {                                \
            g0 += __shfl_xor_sync(0xFFFFFFFFu, g0, off);                    \
            g1 += __shfl_xor_sync(0xFFFFFFFFu, g1, off);                    \
        }                                                                   \
        float e0 = __expf(g0 + bgv);                                        \
        float e1 = __expf(g1 + bgv);                                        \
        aS += e0 + e1;                                                      \
        aV0 = fmaf(e0, p00, fmaf(e1, p01, aV0));                            \
        aV1 = fmaf(e0, p10, fmaf(e1, p11, aV1));                            \
    } while (0)

#define NODE1(M)                                                            \
    do {                                                                    \
        const float4* row = base + (size_t)(M) * 64 + lane * 2;             \
        float4 xa = row[0];                                                 \
        float4 xb = row[1];                                                 \
        float x[8] = {xa.x, xa.y, xa.z, xa.w, xb.x, xb.y, xb.z, xb.w};      \
        float g = 0.f, p0 = 0.f, p1 = 0.f;                                  \
        _Pragma("unroll")                                                   \
        for (int j = 0; j < 8; j++) {                                       \
            g  = fmaf(x[j], wg [j], g);                                     \
            p0 = fmaf(x[j], wo0[j], p0);                                    \
            p1 = fmaf(x[j], wo1[j], p1);                                    \
        }                                                                   \
        _Pragma("unroll")                                                   \
        for (int off = 16; off; off >>= 1)                                  \
            g += __shfl_xor_sync(0xFFFFFFFFu, g, off);                      \
        float e = __expf(g + bgv);                                          \
        aS += e;                                                            \
        aV0 = fmaf(e, p0, aV0);                                             \
        aV1 = fmaf(e, p1, aV1);                                             \
    } while (0)

    // ---- work-stealing tile loop with next-tile prefetch ----
    unsigned int t;
    if (lane == 0) t = atomicAdd(&g_work, 1u);
    t = __shfl_sync(0xFFFFFFFFu, t, 0);

    while (t < (unsigned int)numTiles) {
        unsigned int tNext;
        if (lane == 0) tNext = atomicAdd(&g_work, 1u);   // latency hidden
        tNext = __shfl_sync(0xFFFFFFFFu, tNext, 0);

        const int n0 = (int)t * TILE;
        const int n1 = min(n0 + TILE, N);
        const int sLast = seg[n1 - 1];

        if (sLast == cur) {
            // whole tile in cur (ids sorted, tiles monotonically increasing)
            int m = n0;
#pragma unroll
            for (int k = 0; k < TILE / 2; k++) {
                if (m + 2 <= n1) { NODE2(m); m += 2; }
            }
            if (m < n1) NODE1(m);
        } else {
            // boundary (or first) tile: per-node segment tracking
            for (int m = n0; m < n1; m++) {
                int s = seg[m];
                if (s != cur) {
                    if (cur >= 0) FLUSH(cur);
                    cur = s;
                }
                NODE1(m);
            }
        }

        t = tNext;
    }

    if (cur >= 0) FLUSH(cur);
#undef FLUSH
#undef NODE2
#undef NODE1

    // ---- fused finalize: last CTA to arrive does the [B,2] division ----
    __syncthreads();                       // all warps' flush atomics issued
    __shared__ unsigned int s_last;
    if (threadIdx.x == 0) {
        __threadfence();                   // order atomics before the counter
        unsigned int prev = atomicAdd(&g_done, 1u);
        s_last = (prev == (unsigned int)gridDim.x - 1u) ? 1u : 0u;
    }
    __syncthreads();

    if (s_last) {
        __threadfence();                   // acquire: see all CTAs' atomics
        int b = threadIdx.x;
        if (b < B) {
            float s  = g_accS [b];
            float v0 = g_accV0[b];
            float v1 = g_accV1[b];
            float d  = s + 1e-16f;
            out[2 * b + 0] = v0 / d;
            out[2 * b + 1] = v1 / d;
            // restore the zero-invariant for the next call / graph replay
            g_accS [b] = 0.0f;
            g_accV0[b] = 0.0f;
            g_accV1[b] = 0.0f;
        }
        if (threadIdx.x == 0) {
            g_done = 0u;
            g_work = 0u;
        }
    }
}

extern "C" void kernel_launch(void* const* d_in, const int* in_sizes, int n_in,
                              void* d_out, int out_size)
{
    const float* states = (const float*)d_in[0];
    const int*   seg    = (const int*)  d_in[1];
    const float* Wg     = (const float*)d_in[2];
    const float* bg     = (const float*)d_in[3];
    const float* Wo     = (const float*)d_in[4];
    const float* bo     = (const float*)d_in[5];
    float*       out    = (float*)d_out;

    const int N = in_sizes[1];
    const int B = out_size / 2;

    ga_main<<<NBLOCKS, NTHREADS>>>(states, seg, Wg, bg, Wo, bo, out, N, B);
}

// round 9
// speedup vs baseline: 2.0416x; 2.0416x over previous
#include <cuda_runtime.h>
#include <cuda_bf16.h>

// GlobalAttentionLayer, single fused pass, SINGLE LAUNCH (R9).
// pooled[b] = sum_n e^{g_n} * (states_n @ Wo + bo) / (sum_n e^{g_n} + eps)
//
// R9 = R7 (segment-outer, branch-free x2 inner loop) + hybrid scheduling:
//  - 90% of nodes statically partitioned (one contiguous chunk per warp)
//  - last 10% behind a work queue in 128-node tiles (~780 atomics TOTAL,
//    vs R8's 250K fine-grained grabs that serialized on one L2 slot)
// Early-finishing warps drain the tail pool -> finishing-time spread shrinks.
//
// Inputs (metadata order):
//   d_in[0] states  float32 [N, 256]
//   d_in[1] seg_ids int32   [N]   (sorted)
//   d_in[2] Wg float32 [256,1]   d_in[3] bg float32 [1]
//   d_in[4] Wo float32 [256,2]   d_in[5] bo float32 [2]
// Output: float32 [B, 2], B = out_size/2

#define NBLOCKS   592
#define NTHREADS  256
#define MAXB      1024
#define STEAL_TILE 128

__device__ float        g_accS [MAXB];   // zero at module load; epilogue re-zeros
__device__ float        g_accV0[MAXB];
__device__ float        g_accV1[MAXB];
__device__ unsigned int g_work;          // steal-queue head; epilogue re-zeros
__device__ unsigned int g_done;          // CTA-done counter; epilogue re-zeros

// Process nodes [lo, hi): segment-outer, branch-free x2 inner, flush per segment.
__device__ __forceinline__ void process_range(
    const float4* __restrict__ base,
    const int*    __restrict__ seg,
    const float (&wg)[8], const float (&wo0)[8], const float (&wo1)[8],
    float bgv, float bo0, float bo1,
    int lane, int lo_in, int hi)
{
    int n = lo_in;
    while (n < hi) {
        const int s = seg[n];                // lane-uniform

        // binary search: first index in (n, hi) with seg != s
        int lo = n + 1, hh = hi;
        while (lo < hh) {
            int mid = (lo + hh) >> 1;
            if (seg[mid] == s) lo = mid + 1; else hh = mid;
        }
        const int sEnd = lo;

        float aS = 0.0f, aV0 = 0.0f, aV1 = 0.0f;

        int m = n;
        for (; m + 2 <= sEnd; m += 2) {
            const float4* r0 = base + (size_t)(m + 0) * 64 + lane * 2;
            const float4* r1 = base + (size_t)(m + 1) * 64 + lane * 2;
            float4 xa0 = r0[0];
            float4 xb0 = r0[1];
            float4 xa1 = r1[0];
            float4 xb1 = r1[1];

            float x0[8] = {xa0.x, xa0.y, xa0.z, xa0.w,
                           xb0.x, xb0.y, xb0.z, xb0.w};
            float x1[8] = {xa1.x, xa1.y, xa1.z, xa1.w,
                           xb1.x, xb1.y, xb1.z, xb1.w};

            float g0 = 0.f, p00 = 0.f, p10 = 0.f;
            float g1 = 0.f, p01 = 0.f, p11 = 0.f;
#pragma unroll
            for (int j = 0; j < 8; j++) {
                g0  = fmaf(x0[j], wg [j], g0);
                g1  = fmaf(x1[j], wg [j], g1);
                p00 = fmaf(x0[j], wo0[j], p00);
                p01 = fmaf(x1[j], wo0[j], p01);
                p10 = fmaf(x0[j], wo1[j], p10);
                p11 = fmaf(x1[j], wo1[j], p11);
            }
#pragma unroll
            for (int off = 16; off; off >>= 1) {
                g0 += __shfl_xor_sync(0xFFFFFFFFu, g0, off);
                g1 += __shfl_xor_sync(0xFFFFFFFFu, g1, off);
            }
            float e0 = __expf(g0 + bgv);
            float e1 = __expf(g1 + bgv);
            aS += e0 + e1;
            aV0 = fmaf(e0, p00, fmaf(e1, p01, aV0));
            aV1 = fmaf(e0, p10, fmaf(e1, p11, aV1));
        }
        for (; m < sEnd; m++) {
            const float4* row = base + (size_t)m * 64 + lane * 2;
            float4 xa = row[0];
            float4 xb = row[1];
            float x[8] = {xa.x, xa.y, xa.z, xa.w, xb.x, xb.y, xb.z, xb.w};
            float g = 0.f, p0 = 0.f, p1 = 0.f;
#pragma unroll
            for (int j = 0; j < 8; j++) {
                g  = fmaf(x[j], wg [j], g);
                p0 = fmaf(x[j], wo0[j], p0);
                p1 = fmaf(x[j], wo1[j], p1);
            }
#pragma unroll
            for (int off = 16; off; off >>= 1)
                g += __shfl_xor_sync(0xFFFFFFFFu, g, off);
            float e = __expf(g + bgv);
            aS += e;
            aV0 = fmaf(e, p0, aV0);
            aV1 = fmaf(e, p1, aV1);
        }

        // flush this segment
        {
            float v0 = aV0, v1 = aV1;
#pragma unroll
            for (int off = 16; off; off >>= 1) {
                v0 += __shfl_xor_sync(0xFFFFFFFFu, v0, off);
                v1 += __shfl_xor_sync(0xFFFFFFFFu, v1, off);
            }
            if (lane == 0) {
                atomicAdd(&g_accS [s], aS);
                atomicAdd(&g_accV0[s], fmaf(bo0, aS, v0));
                atomicAdd(&g_accV1[s], fmaf(bo1, aS, v1));
            }
        }

        n = sEnd;
    }
}

__global__ __launch_bounds__(NTHREADS) void ga_main(
    const float* __restrict__ states,
    const int*   __restrict__ seg,
    const float* __restrict__ Wg,
    const float* __restrict__ bg,
    const float* __restrict__ Wo,
    const float* __restrict__ bo,
    float* __restrict__ out,
    int N, int B)
{
    const int lane   = threadIdx.x & 31;
    const int gwarp  = (blockIdx.x * blockDim.x + threadIdx.x) >> 5;
    const int nwarps = (gridDim.x * blockDim.x) >> 5;

    const float bgv = bg[0];
    const float bo0 = bo[0];
    const float bo1 = bo[1];

    // Per-lane slice of the weight vectors: columns [lane*8, lane*8+8)
    const int c0 = lane * 8;
    float wg[8], wo0[8], wo1[8];
#pragma unroll
    for (int j = 0; j < 8; j++) {
        wg [j] = Wg[c0 + j];
        wo0[j] = Wo[(c0 + j) * 2 + 0];
        wo1[j] = Wo[(c0 + j) * 2 + 1];
    }

    const float4* base = reinterpret_cast<const float4*>(states);

    // ---- static part: 90% of N, one contiguous chunk per warp ----
    const int chunk       = (int)(((long long)N * 9) / (10LL * nwarps));
    const int staticTotal = chunk * nwarps;
    {
        const int start = gwarp * chunk;
        const int end   = start + chunk;     // <= staticTotal <= N
        if (start < end)
            process_range(base, seg, wg, wo0, wo1, bgv, bo0, bo1,
                          lane, start, end);
    }

    // ---- steal tail: [staticTotal, N) in 128-node tiles (~780 grabs) ----
    {
        const int tailN    = N - staticTotal;
        const int numTiles = (tailN + STEAL_TILE - 1) / STEAL_TILE;
        for (;;) {
            unsigned int t;
            if (lane == 0) t = atomicAdd(&g_work, 1u);
            t = __shfl_sync(0xFFFFFFFFu, t, 0);
            if (t >= (unsigned int)numTiles) break;

            const int lo = staticTotal + (int)t * STEAL_TILE;
            const int hi = min(lo + STEAL_TILE, N);
            process_range(base, seg, wg, wo0, wo1, bgv, bo0, bo1,
                          lane, lo, hi);
        }
    }

    // ---- fused finalize: last CTA to arrive does the [B,2] division ----
    __syncthreads();                       // all warps' flush atomics issued
    __shared__ unsigned int s_last;
    if (threadIdx.x == 0) {
        __threadfence();                   // order atomics before the counter
        unsigned int prev = atomicAdd(&g_done, 1u);
        s_last = (prev == (unsigned int)gridDim.x - 1u) ? 1u : 0u;
    }
    __syncthreads();

    if (s_last) {
        __threadfence();                   // acquire: see all CTAs' atomics
        int b = threadIdx.x;
        if (b < B) {
            float s  = g_accS [b];
            float v0 = g_accV0[b];
            float v1 = g_accV1[b];
            float d  = s + 1e-16f;
            out[2 * b + 0] = v0 / d;
            out[2 * b + 1] = v1 / d;
            // restore the zero-invariant for the next call / graph replay
            g_accS [b] = 0.0f;
            g_accV0[b] = 0.0f;
            g_accV1[b] = 0.0f;
        }
        if (threadIdx.x == 0) {
            g_done = 0u;
            g_work = 0u;
        }
    }
}

extern "C" void kernel_launch(void* const* d_in, const int* in_sizes, int n_in,
                              void* d_out, int out_size)
{
    const float* states = (const float*)d_in[0];
    const int*   seg    = (const int*)  d_in[1];
    const float* Wg     = (const float*)d_in[2];
    const float* bg     = (const float*)d_in[3];
    const float* Wo     = (const float*)d_in[4];
    const float* bo     = (const float*)d_in[5];
    float*       out    = (float*)d_out;

    const int N = in_sizes[1];
    const int B = out_size / 2;

    ga_main<<<NBLOCKS, NTHREADS>>>(states, seg, Wg, bg, Wo, bo, out, N, B);
}

// round 10
// speedup vs baseline: 2.3380x; 1.1452x over previous
#include <cuda_runtime.h>
#include <cuda_bf16.h>

// GlobalAttentionLayer, single fused pass, SINGLE LAUNCH (R10).
// pooled[b] = sum_n e^{g_n} * (states_n @ Wo + bo) / (sum_n e^{g_n} + eps)
//
// R10 = R7 verbatim (best: 160.6us; segment-outer, branch-free x2 inner,
// static per-warp chunks — dynamic scheduling confirmed-regressive in R8/R9)
// + __ldcs streaming hints on the states rows (read-once, 1GB through a
// 126MB L2: evict-first reduces L2 replacement churn).
//
// Inputs (metadata order):
//   d_in[0] states  float32 [N, 256]
//   d_in[1] seg_ids int32   [N]   (sorted)
//   d_in[2] Wg float32 [256,1]   d_in[3] bg float32 [1]
//   d_in[4] Wo float32 [256,2]   d_in[5] bo float32 [2]
// Output: float32 [B, 2], B = out_size/2

#define NBLOCKS  592
#define NTHREADS 256
#define MAXB     1024

__device__ float        g_accS [MAXB];   // zero at module load; epilogue re-zeros
__device__ float        g_accV0[MAXB];
__device__ float        g_accV1[MAXB];
__device__ unsigned int g_done;          // zero at module load; epilogue re-zeros

__global__ __launch_bounds__(NTHREADS) void ga_main(
    const float* __restrict__ states,
    const int*   __restrict__ seg,
    const float* __restrict__ Wg,
    const float* __restrict__ bg,
    const float* __restrict__ Wo,
    const float* __restrict__ bo,
    float* __restrict__ out,
    int N, int B)
{
    const int lane   = threadIdx.x & 31;
    const int gwarp  = (blockIdx.x * blockDim.x + threadIdx.x) >> 5;
    const int nwarps = (gridDim.x * blockDim.x) >> 5;
    const int chunk  = (N + nwarps - 1) / nwarps;
    const int start  = gwarp * chunk;
    const int end    = min(start + chunk, N);

    const float bgv = bg[0];
    const float bo0 = bo[0];
    const float bo1 = bo[1];

    if (start < end) {
        // Per-lane slice of the weight vectors: columns [lane*8, lane*8+8)
        const int c0 = lane * 8;
        float wg[8], wo0[8], wo1[8];
#pragma unroll
        for (int j = 0; j < 8; j++) {
            wg [j] = Wg[c0 + j];
            wo0[j] = Wo[(c0 + j) * 2 + 0];
            wo1[j] = Wo[(c0 + j) * 2 + 1];
        }

        const float4* base = reinterpret_cast<const float4*>(states);

        int n = start;
        while (n < end) {
            const int s = seg[n];            // current segment id (lane-uniform)

            // binary search: first index in (n, end) with seg != s
            int lo = n + 1, hi = end;
            while (lo < hi) {
                int mid = (lo + hi) >> 1;
                if (seg[mid] == s) lo = mid + 1; else hi = mid;
            }
            const int sEnd = lo;

            float aS  = 0.0f;                // sum of e (lane-uniform)
            float aV0 = 0.0f, aV1 = 0.0f;    // per-lane partials of e * p_lane

            int m = n;
            // ---- branch-free inner loop: 2 nodes/iter, streaming loads ----
            for (; m + 2 <= sEnd; m += 2) {
                const float4* r0 = base + (size_t)(m + 0) * 64 + lane * 2;
                const float4* r1 = base + (size_t)(m + 1) * 64 + lane * 2;
                float4 xa0 = __ldcs(r0);
                float4 xb0 = __ldcs(r0 + 1);
                float4 xa1 = __ldcs(r1);
                float4 xb1 = __ldcs(r1 + 1);

                float x0[8] = {xa0.x, xa0.y, xa0.z, xa0.w,
                               xb0.x, xb0.y, xb0.z, xb0.w};
                float x1[8] = {xa1.x, xa1.y, xa1.z, xa1.w,
                               xb1.x, xb1.y, xb1.z, xb1.w};

                float g0 = 0.f, p00 = 0.f, p10 = 0.f;
                float g1 = 0.f, p01 = 0.f, p11 = 0.f;
#pragma unroll
                for (int j = 0; j < 8; j++) {
                    g0  = fmaf(x0[j], wg [j], g0);
                    g1  = fmaf(x1[j], wg [j], g1);
                    p00 = fmaf(x0[j], wo0[j], p00);
                    p01 = fmaf(x1[j], wo0[j], p01);
                    p10 = fmaf(x0[j], wo1[j], p10);
                    p11 = fmaf(x1[j], wo1[j], p11);
                }

                // two interleaved butterfly chains (gates only)
#pragma unroll
                for (int off = 16; off; off >>= 1) {
                    g0 += __shfl_xor_sync(0xFFFFFFFFu, g0, off);
                    g1 += __shfl_xor_sync(0xFFFFFFFFu, g1, off);
                }

                float e0 = __expf(g0 + bgv);
                float e1 = __expf(g1 + bgv);

                aS += e0 + e1;
                aV0 = fmaf(e0, p00, fmaf(e1, p01, aV0));
                aV1 = fmaf(e0, p10, fmaf(e1, p11, aV1));
            }

            // ---- tail (at most 1 node of this segment) ----
            for (; m < sEnd; m++) {
                const float4* row = base + (size_t)m * 64 + lane * 2;
                float4 xa = __ldcs(row);
                float4 xb = __ldcs(row + 1);

                float x[8] = {xa.x, xa.y, xa.z, xa.w,
                              xb.x, xb.y, xb.z, xb.w};
                float g = 0.f, p0 = 0.f, p1 = 0.f;
#pragma unroll
                for (int j = 0; j < 8; j++) {
                    g  = fmaf(x[j], wg [j], g);
                    p0 = fmaf(x[j], wo0[j], p0);
                    p1 = fmaf(x[j], wo1[j], p1);
                }
#pragma unroll
                for (int off = 16; off; off >>= 1)
                    g += __shfl_xor_sync(0xFFFFFFFFu, g, off);

                float e = __expf(g + bgv);
                aS += e;
                aV0 = fmaf(e, p0, aV0);
                aV1 = fmaf(e, p1, aV1);
            }

            // ---- flush this segment (once per segment per warp) ----
            {
                float v0 = aV0, v1 = aV1;
#pragma unroll
                for (int off = 16; off; off >>= 1) {
                    v0 += __shfl_xor_sync(0xFFFFFFFFu, v0, off);
                    v1 += __shfl_xor_sync(0xFFFFFFFFu, v1, off);
                }
                if (lane == 0) {
                    atomicAdd(&g_accS [s], aS);
                    atomicAdd(&g_accV0[s], fmaf(bo0, aS, v0));
                    atomicAdd(&g_accV1[s], fmaf(bo1, aS, v1));
                }
            }

            n = sEnd;
        }
    }

    // ---- fused finalize: last CTA to arrive does the [B,2] division ----
    __syncthreads();                       // all warps' flush atomics issued
    __shared__ unsigned int s_last;
    if (threadIdx.x == 0) {
        __threadfence();                   // order atomics before the counter
        unsigned int prev = atomicAdd(&g_done, 1u);
        s_last = (prev == (unsigned int)gridDim.x - 1u) ? 1u : 0u;
    }
    __syncthreads();

    if (s_last) {
        __threadfence();                   // acquire: see all CTAs' atomics
        int b = threadIdx.x;
        if (b < B) {
            float s  = g_accS [b];
            float v0 = g_accV0[b];
            float v1 = g_accV1[b];
            float d  = s + 1e-16f;
            out[2 * b + 0] = v0 / d;
            out[2 * b + 1] = v1 / d;
            // restore the zero-invariant for the next call / graph replay
            g_accS [b] = 0.0f;
            g_accV0[b] = 0.0f;
            g_accV1[b] = 0.0f;
        }
        if (threadIdx.x == 0) g_done = 0u;
    }
}

extern "C" void kernel_launch(void* const* d_in, const int* in_sizes, int n_in,
                              void* d_out, int out_size)
{
    const float* states = (const float*)d_in[0];
    const int*   seg    = (const int*)  d_in[1];
    const float* Wg     = (const float*)d_in[2];
    const float* bg     = (const float*)d_in[3];
    const float* Wo     = (const float*)d_in[4];
    const float* bo     = (const float*)d_in[5];
    float*       out    = (float*)d_out;

    const int N = in_sizes[1];
    const int B = out_size / 2;

    ga_main<<<NBLOCKS, NTHREADS>>>(states, seg, Wg, bg, Wo, bo, out, N, B);
}